// round 2
// baseline (speedup 1.0000x reference)
#include <cuda_runtime.h>
#include <math.h>

typedef unsigned long long ull;

#define BB 8
#define SS 2048
#define DM 256
#define NH 4
#define DKK 64
#define NROWS (BB*SS)   // 16384

// ---- scratch (static device, no allocations) ----
__device__ float g_qs[BB*NH*SS*DKK];     // pre-scaled by 1/8
__device__ float g_ks[BB*NH*SS*DKK];
__device__ float g_vs[BB*SS*DKK];
__device__ float g_heads[BB*NH*SS*DKK];

// ---- packed fp32x2 helpers (FFMA2: double-rate fp32 on sm_103a) ----
__device__ __forceinline__ void fma2(ull& d, ull a, ull b) {
    asm("fma.rn.f32x2 %0, %1, %2, %0;" : "+l"(d) : "l"(a), "l"(b));
}
__device__ __forceinline__ ull pk2(float x, float y) {
    ull r; asm("mov.b64 %0, {%1, %2};" : "=l"(r) : "f"(x), "f"(y)); return r;
}
__device__ __forceinline__ float2 upk(ull v) {
    float2 r; asm("mov.b64 {%0, %1}, %2;" : "=f"(r.x), "=f"(r.y) : "l"(v)); return r;
}

// =====================================================================
// Kernel 1: projections.  grid(128, 9), block 256.
//   y = 0..3 : qs head y (scaled 0.125), 4..7 : ks head y-4, 8 : vs
//   Reduction-packed f32x2: acc halves hold (d-even, d-odd) partials.
//   A and W both read d-contiguous -> NO transpose, straight copies.
// =====================================================================
#define PROJ_SMEM_BYTES ((128*34 + 64*33) * 8)

__global__ __launch_bounds__(256) void proj_kernel(
    const float* __restrict__ qin, const float* __restrict__ kin,
    const float* __restrict__ vin,
    const float* __restrict__ Wq, const float* __restrict__ bq,
    const float* __restrict__ Wk, const float* __restrict__ bk,
    const float* __restrict__ Wv, const float* __restrict__ bv)
{
    extern __shared__ ull smp[];
    ull* As = smp;            // [128][34] ull : rows x 32 d-pairs (pitch 34)
    ull* Ws = smp + 128*34;   // [64][33]  ull : e    x 32 d-pairs (pitch 33)

    int p = blockIdx.y;
    const float *A, *W, *bias;
    float scale; float* dst; int h = 0;
    if (p < 4)      { h = p;   A = qin; W = Wq + h*DKK*DM; bias = bq + h*DKK; scale = 0.125f; dst = g_qs; }
    else if (p < 8) { h = p-4; A = kin; W = Wk + h*DKK*DM; bias = bk + h*DKK; scale = 1.0f;   dst = g_ks; }
    else            {          A = vin; W = Wv;            bias = bv;         scale = 1.0f;   dst = g_vs; }

    int row0 = blockIdx.x * 128;
    int tid  = threadIdx.x;
    int rowg = tid >> 4;     // 0..15 -> 8 rows each
    int eg   = tid & 15;     // e = eg + 16*j

    ull acc[8][4];
#pragma unroll
    for (int i = 0; i < 8; i++)
#pragma unroll
        for (int j = 0; j < 4; j++) acc[i][j] = 0ull;

    for (int d0 = 0; d0 < DM; d0 += 64) {
        __syncthreads();
        // stage A tile: 128 rows x 64 d (2048 float4), coalesced, STS.128
#pragma unroll
        for (int i = 0; i < 8; i++) {
            int f4 = tid + i*256;
            int r = f4 >> 4, f = f4 & 15;
            float4 v = *(const float4*)(A + (size_t)(row0 + r)*DM + d0 + f*4);
            *(float4*)&As[r*34 + 2*f] = v;
        }
        // stage W tile: 64 e x 64 d (1024 float4), coalesced
#pragma unroll
        for (int i = 0; i < 4; i++) {
            int f4 = tid + i*256;
            int e = f4 >> 4, f = f4 & 15;
            float4 v = *(const float4*)(W + (size_t)e*DM + d0 + f*4);
            ulonglong2 u = *(ulonglong2*)&v;
            Ws[e*33 + 2*f]     = u.x;
            Ws[e*33 + 2*f + 1] = u.y;
        }
        __syncthreads();

#pragma unroll 8
        for (int dp = 0; dp < 32; dp++) {
            ull w0 = Ws[(eg     )*33 + dp];
            ull w1 = Ws[(eg + 16)*33 + dp];
            ull w2 = Ws[(eg + 32)*33 + dp];
            ull w3 = Ws[(eg + 48)*33 + dp];
#pragma unroll
            for (int i = 0; i < 8; i++) {
                ull a = As[(rowg*8 + i)*34 + dp];
                fma2(acc[i][0], a, w0);
                fma2(acc[i][1], a, w1);
                fma2(acc[i][2], a, w2);
                fma2(acc[i][3], a, w3);
            }
        }
    }

#pragma unroll
    for (int i = 0; i < 8; i++) {
        int gr = row0 + rowg*8 + i;          // = b*SS + s
        int bb = gr >> 11;
        int s  = gr & (SS-1);
        size_t base;
        if (p < 8) base = ((size_t)(bb*NH + h)*SS + s)*DKK;
        else       base = (size_t)gr*DKK;
#pragma unroll
        for (int j = 0; j < 4; j++) {
            int e = eg + 16*j;
            float2 xy = upk(acc[i][j]);
            dst[base + e] = (xy.x + xy.y + bias[e]) * scale;
        }
    }
}

// =====================================================================
// Kernel 2: fused scores + softmax + attn write + PV.  grid(128,4,8), blk 256.
//   smem: S_[16][2048] 128KB | KV 17408f (K ull-tile / V tile / red) |
//         QT 16x33 ull | invrow[16]
// =====================================================================
#define SM2_F (32768 + 17408 + 1056 + 16)     // floats -> 204,992 B

__global__ __launch_bounds__(256) void attn_kernel(float* __restrict__ attn_out)
{
    extern __shared__ float sm[];
    float* S_     = sm;                         // 16 x 2048
    float* KV     = sm + 32768;                 // shared region
    ull*   KT     = (ull*)KV;                   // K tile [256][34] ull
    ull*   QT     = (ull*)(sm + 32768 + 17408); // Q [16][33] ull
    float* invrow = sm + 32768 + 17408 + 1056;  // 16

    int b  = blockIdx.z;
    int h  = blockIdx.y;
    int q0 = blockIdx.x * 16;
    int tid = threadIdx.x;

    const float* qsb = g_qs + ((size_t)(b*NH + h)*SS)*DKK;
    const float* ksb = g_ks + ((size_t)(b*NH + h)*SS)*DKK;
    const float* vsb = g_vs + (size_t)b*SS*DKK;

    // ---- load Q chunk as d-pairs: QT[q][dp] ----
    {
        int q = tid >> 4, f = tid & 15;
        float4 v4 = *(const float4*)(qsb + (size_t)(q0 + q)*DKK + f*4);
        QT[q*33 + 2*f]     = pk2(v4.x, v4.y);
        QT[q*33 + 2*f + 1] = pk2(v4.z, v4.w);
    }

    // ---- Phase 1: scores via reduction-packed f32x2 ----
    int qg = tid >> 7;       // 0..1  : q = qg*8 + i
    int ki = tid & 127;      // k lanes: k = ki and ki+128
    for (int kt = 0; kt < 8; kt++) {
        int k0 = kt * 256;
        __syncthreads();
        // stage K tile [256 k][32 dp] pitch 34 (straight float4 copy)
#pragma unroll
        for (int i = 0; i < 16; i++) {
            int f4 = tid + i*256;
            int key = f4 >> 4, f = f4 & 15;
            float4 v4 = *(const float4*)(ksb + (size_t)(k0 + key)*DKK + f*4);
            *(float4*)&KT[key*34 + 2*f] = v4;
        }
        __syncthreads();

        ull acc[8][2];
#pragma unroll
        for (int i = 0; i < 8; i++) { acc[i][0] = 0ull; acc[i][1] = 0ull; }

#pragma unroll 8
        for (int dp = 0; dp < 32; dp++) {
            ull kk0 = KT[(size_t)ki*34 + dp];
            ull kk1 = KT[(size_t)(ki + 128)*34 + dp];
#pragma unroll
            for (int i = 0; i < 8; i++) {
                ull qq = QT[(qg*8 + i)*33 + dp];
                fma2(acc[i][0], qq, kk0);
                fma2(acc[i][1], qq, kk1);
            }
        }
#pragma unroll
        for (int i = 0; i < 8; i++) {
            float2 a0 = upk(acc[i][0]);
            float2 a1 = upk(acc[i][1]);
            S_[(size_t)(qg*8 + i)*2048 + k0 + ki]       = a0.x + a0.y;
            S_[(size_t)(qg*8 + i)*2048 + k0 + ki + 128] = a1.x + a1.y;
        }
    }
    __syncthreads();

    // ---- Phase 2: softmax (unnormalized exp kept in S_) ----
    {
        int row = tid >> 4;
        int l16 = tid & 15;
        float4* S4 = (float4*)(S_ + row*2048);
        float m = -1e30f;
#pragma unroll 8
        for (int i = 0; i < 32; i++) {
            float4 x = S4[i*16 + l16];
            m = fmaxf(m, fmaxf(fmaxf(x.x, x.y), fmaxf(x.z, x.w)));
        }
#pragma unroll
        for (int off = 8; off >= 1; off >>= 1)
            m = fmaxf(m, __shfl_xor_sync(0xffffffffu, m, off));
        float ssum = 0.0f;
#pragma unroll 4
        for (int i = 0; i < 32; i++) {
            int idx = i*16 + l16;
            float4 x = S4[idx];
            x.x = __expf(x.x - m); x.y = __expf(x.y - m);
            x.z = __expf(x.z - m); x.w = __expf(x.w - m);
            S4[idx] = x;
            ssum += (x.x + x.y) + (x.z + x.w);
        }
#pragma unroll
        for (int off = 8; off >= 1; off >>= 1)
            ssum += __shfl_xor_sync(0xffffffffu, ssum, off);
        if (l16 == 0) invrow[row] = 1.0f / ssum;
    }
    __syncthreads();

    // ---- Phase 2b: normalized attn -> gmem ----
    {
        float* ab = attn_out + (((size_t)b*SS + q0)*NH + h)*SS;
#pragma unroll 4
        for (int it = 0; it < 32; it++) {
            int slot = tid + it*256;
            int r  = slot >> 9;
            int c4 = slot & 511;
            float4 x = ((float4*)(S_ + r*2048))[c4];
            float inv = invrow[r];
            x.x *= inv; x.y *= inv; x.z *= inv; x.w *= inv;
            ((float4*)(ab + (size_t)r*NH*SS))[c4] = x;
        }
    }

    // ---- Phase 3: PV, e-pair packed f32x2, k split 4-way ----
    int kg = tid >> 6;          // 0..3 k-quarter
    int tq = (tid >> 3) & 7;    // 2 q each
    int te = tid & 7;           // e = te*8 .. te*8+7
    ull acc2[2][4];
#pragma unroll
    for (int j = 0; j < 2; j++)
#pragma unroll
        for (int ep = 0; ep < 4; ep++) acc2[j][ep] = 0ull;

    float* Vs = KV;             // [256][64] floats
    for (int vt = 0; vt < 8; vt++) {
        int k0 = vt * 256;
        __syncthreads();
        {
            const float4* src = (const float4*)(vsb + (size_t)k0*DKK);
            float4* dst4 = (float4*)Vs;
#pragma unroll
            for (int i = 0; i < 16; i++) {
                int f4 = tid + i*256;
                dst4[f4] = src[f4];
            }
        }
        __syncthreads();
#pragma unroll 8
        for (int kk = 0; kk < 64; kk++) {
            int kl = kg*64 + kk;
            ulonglong2 V0 = *(ulonglong2*)&Vs[kl*64 + te*8];
            ulonglong2 V1 = *(ulonglong2*)&Vs[kl*64 + te*8 + 4];
            float p0 = S_[(size_t)(tq*2 + 0)*2048 + k0 + kl];
            float p1 = S_[(size_t)(tq*2 + 1)*2048 + k0 + kl];
            ull pd0 = pk2(p0, p0);
            ull pd1 = pk2(p1, p1);
            fma2(acc2[0][0], pd0, V0.x);
            fma2(acc2[0][1], pd0, V0.y);
            fma2(acc2[0][2], pd0, V1.x);
            fma2(acc2[0][3], pd0, V1.y);
            fma2(acc2[1][0], pd1, V0.x);
            fma2(acc2[1][1], pd1, V0.y);
            fma2(acc2[1][2], pd1, V1.x);
            fma2(acc2[1][3], pd1, V1.y);
        }
    }
    __syncthreads();
    // reduce 4 k-quarters through smem (red = KV region)
    {
        float* red = KV;   // [4][16][64]
#pragma unroll
        for (int j = 0; j < 2; j++)
#pragma unroll
            for (int ep = 0; ep < 4; ep++)
                *(ull*)&red[(size_t)((kg*16 + tq*2 + j)*64) + te*8 + ep*2] = acc2[j][ep];
    }
    __syncthreads();
    {
        float* red = KV;
        int qq = tid >> 4;
        int e4 = tid & 15;
        float4 o = make_float4(0.f, 0.f, 0.f, 0.f);
#pragma unroll
        for (int g = 0; g < 4; g++) {
            float4 t = ((float4*)red)[(g*16 + qq)*16 + e4];
            o.x += t.x; o.y += t.y; o.z += t.z; o.w += t.w;
        }
        float inv = invrow[qq];
        o.x *= inv; o.y *= inv; o.z *= inv; o.w *= inv;
        *(float4*)(g_heads + ((size_t)(b*NH + h)*SS + q0 + qq)*DKK + e4*4) = o;
    }
}

// =====================================================================
// Kernel 3: head-average + output projection (unchanged).
// =====================================================================
#define SMEM3_FLOATS (64*68 + 64*260)

__global__ __launch_bounds__(256) void outproj_kernel(
    const float* __restrict__ Wh, float* __restrict__ out)
{
    extern __shared__ float sm[];
    float* AvT = sm;             // [e][s] 64x68
    float* WhT = sm + 64*68;     // [e][dm] 64x260

    int s0 = blockIdx.x * 64;
    int tid = threadIdx.x;

#pragma unroll
    for (int i = 0; i < 16; i++) {
        int idx = tid + i*256;
        int sl = idx >> 6, e = idx & 63;
        int gr = s0 + sl;
        int bb = gr >> 11, s = gr & (SS-1);
        size_t base = ((size_t)bb*NH*SS + s)*DKK + e;
        float sum = g_heads[base]
                  + g_heads[base + (size_t)SS*DKK]
                  + g_heads[base + (size_t)2*SS*DKK]
                  + g_heads[base + (size_t)3*SS*DKK];
        AvT[e*68 + sl] = 0.25f * sum;
    }
#pragma unroll
    for (int i = 0; i < 64; i++) {
        int idx = tid + i*256;
        int dm = idx >> 6, e = idx & 63;
        WhT[e*260 + dm] = Wh[dm*DKK + e];
    }
    __syncthreads();

    int ts = tid >> 5;
    int tc = tid & 31;
    float acc[8][8];
#pragma unroll
    for (int i = 0; i < 8; i++)
#pragma unroll
        for (int j = 0; j < 8; j++) acc[i][j] = 0.0f;

#pragma unroll 8
    for (int e = 0; e < 64; e++) {
        float4 a0 = *(float4*)(AvT + e*68 + ts*8);
        float4 a1 = *(float4*)(AvT + e*68 + ts*8 + 4);
        float4 w0 = *(float4*)(WhT + e*260 + tc*8);
        float4 w1 = *(float4*)(WhT + e*260 + tc*8 + 4);
        float a[8] = {a0.x,a0.y,a0.z,a0.w,a1.x,a1.y,a1.z,a1.w};
        float w[8] = {w0.x,w0.y,w0.z,w0.w,w1.x,w1.y,w1.z,w1.w};
#pragma unroll
        for (int i = 0; i < 8; i++)
#pragma unroll
            for (int j = 0; j < 8; j++) acc[i][j] = fmaf(a[i], w[j], acc[i][j]);
    }
#pragma unroll
    for (int i = 0; i < 8; i++) {
        int gr = s0 + ts*8 + i;
        float4 o0 = make_float4(acc[i][0], acc[i][1], acc[i][2], acc[i][3]);
        float4 o1 = make_float4(acc[i][4], acc[i][5], acc[i][6], acc[i][7]);
        *(float4*)(out + (size_t)gr*DM + tc*8)     = o0;
        *(float4*)(out + (size_t)gr*DM + tc*8 + 4) = o1;
    }
}

// =====================================================================
extern "C" void kernel_launch(void* const* d_in, const int* in_sizes, int n_in,
                              void* d_out, int out_size)
{
    const float* q  = (const float*)d_in[0];
    const float* k  = (const float*)d_in[1];
    const float* v  = (const float*)d_in[2];
    const float* Wq = (const float*)d_in[3];
    const float* bq = (const float*)d_in[4];
    const float* Wk = (const float*)d_in[5];
    const float* bk = (const float*)d_in[6];
    const float* Wv = (const float*)d_in[7];
    const float* bv = (const float*)d_in[8];
    const float* Wh = (const float*)d_in[9];

    float* out  = (float*)d_out;                       // [B,S,DM]
    float* attn = out + (size_t)BB*SS*DM;              // [B,S,H,S]

    cudaFuncSetAttribute(proj_kernel, cudaFuncAttributeMaxDynamicSharedMemorySize,
                         PROJ_SMEM_BYTES);
    cudaFuncSetAttribute(attn_kernel, cudaFuncAttributeMaxDynamicSharedMemorySize,
                         SM2_F * sizeof(float));
    cudaFuncSetAttribute(outproj_kernel, cudaFuncAttributeMaxDynamicSharedMemorySize,
                         SMEM3_FLOATS * sizeof(float));

    proj_kernel<<<dim3(NROWS/128, 9), 256, PROJ_SMEM_BYTES>>>(q, k, v, Wq, bq, Wk, bk, Wv, bv);
    attn_kernel<<<dim3(SS/16, NH, BB), 256, SM2_F * sizeof(float)>>>(attn);
    outproj_kernel<<<NROWS/64, 256, SMEM3_FLOATS * sizeof(float)>>>(Wh, out);
}

// round 4
// speedup vs baseline: 1.4279x; 1.4279x over previous
#include <cuda_runtime.h>
#include <cuda_bf16.h>
#include <math.h>

typedef unsigned long long ull;
typedef unsigned int u32;

#define BB 8
#define SS 2048
#define DM 256
#define NH 4
#define DKK 64
#define NROWS (BB*SS)   // 16384

// ---- scratch (static device, no allocations) ----
__device__ float g_qs[BB*NH*SS*DKK];     // pre-scaled by 1/8
__device__ float g_ks[BB*NH*SS*DKK];
__device__ float g_vs[BB*SS*DKK];
__device__ float g_heads[BB*NH*SS*DKK];
// packed bf16x2 hi/lo planes (d-pairs): [bh][s][32] u32
#define QKPAIRS (BB*NH*SS*32)            // 2,097,152
__device__ u32 g_qhi[QKPAIRS];
__device__ u32 g_qlo[QKPAIRS];
__device__ u32 g_khi[QKPAIRS];
__device__ u32 g_klo[QKPAIRS];
// transposed V, key-pairs packed: [b][e][S/2] u32
#define VTP (BB*DKK*(SS/2))              // 524,288
__device__ u32 g_vthi[VTP];
__device__ u32 g_vtlo[VTP];

// ---- packed fp32x2 helpers (proj kernel) ----
__device__ __forceinline__ void fma2(ull& d, ull a, ull b) {
    asm("fma.rn.f32x2 %0, %1, %2, %0;" : "+l"(d) : "l"(a), "l"(b));
}
__device__ __forceinline__ float2 upk(ull v) {
    float2 r; asm("mov.b64 {%0, %1}, %2;" : "=f"(r.x), "=f"(r.y) : "l"(v)); return r;
}

// ---- bf16 helpers ----
// pack two floats -> bf16x2 (lo -> low 16 bits)
__device__ __forceinline__ u32 bf2(float lo, float hi) {
    u32 r; asm("cvt.rn.bf16x2.f32 %0, %1, %2;" : "=r"(r) : "f"(hi), "f"(lo)); return r;
}
__device__ __forceinline__ float bflo(u32 p) { return __uint_as_float(p << 16); }
__device__ __forceinline__ float bfhi(u32 p) { return __uint_as_float(p & 0xffff0000u); }
// split float2 into hi/lo bf16x2 words
__device__ __forceinline__ void split2(float2 p, u32& hi, u32& lo) {
    hi = bf2(p.x, p.y);
    lo = bf2(p.x - bflo(hi), p.y - bfhi(hi));
}

// ---- bf16 mma m16n8k16, fp32 accumulate ----
__device__ __forceinline__ void mma_bf(float* c, const u32* a, u32 b0, u32 b1) {
    asm volatile("mma.sync.aligned.m16n8k16.row.col.f32.bf16.bf16.f32 "
        "{%0,%1,%2,%3}, {%4,%5,%6,%7}, {%8,%9}, {%0,%1,%2,%3};"
        : "+f"(c[0]), "+f"(c[1]), "+f"(c[2]), "+f"(c[3])
        : "r"(a[0]), "r"(a[1]), "r"(a[2]), "r"(a[3]), "r"(b0), "r"(b1));
}

// =====================================================================
// Kernel 1: projections (round-2 FFMA2, fp32 out). grid(128,9), blk 256.
// =====================================================================
#define PROJ_SMEM_BYTES ((128*34 + 64*33) * 8)

__global__ __launch_bounds__(256) void proj_kernel(
    const float* __restrict__ qin, const float* __restrict__ kin,
    const float* __restrict__ vin,
    const float* __restrict__ Wq, const float* __restrict__ bq,
    const float* __restrict__ Wk, const float* __restrict__ bk,
    const float* __restrict__ Wv, const float* __restrict__ bv)
{
    extern __shared__ ull smp[];
    ull* As = smp;            // [128][34] ull
    ull* Ws = smp + 128*34;   // [64][33]  ull

    int p = blockIdx.y;
    const float *A, *W, *bias;
    float scale; float* dst; int h = 0;
    if (p < 4)      { h = p;   A = qin; W = Wq + h*DKK*DM; bias = bq + h*DKK; scale = 0.125f; dst = g_qs; }
    else if (p < 8) { h = p-4; A = kin; W = Wk + h*DKK*DM; bias = bk + h*DKK; scale = 1.0f;   dst = g_ks; }
    else            {          A = vin; W = Wv;            bias = bv;         scale = 1.0f;   dst = g_vs; }

    int row0 = blockIdx.x * 128;
    int tid  = threadIdx.x;
    int rowg = tid >> 4;
    int eg   = tid & 15;

    ull acc[8][4];
#pragma unroll
    for (int i = 0; i < 8; i++)
#pragma unroll
        for (int j = 0; j < 4; j++) acc[i][j] = 0ull;

    for (int d0 = 0; d0 < DM; d0 += 64) {
        __syncthreads();
#pragma unroll
        for (int i = 0; i < 8; i++) {
            int f4 = tid + i*256;
            int r = f4 >> 4, f = f4 & 15;
            float4 v = *(const float4*)(A + (size_t)(row0 + r)*DM + d0 + f*4);
            *(float4*)&As[r*34 + 2*f] = v;
        }
#pragma unroll
        for (int i = 0; i < 4; i++) {
            int f4 = tid + i*256;
            int e = f4 >> 4, f = f4 & 15;
            float4 v = *(const float4*)(W + (size_t)e*DM + d0 + f*4);
            ulonglong2 u = *(ulonglong2*)&v;
            Ws[e*33 + 2*f]     = u.x;
            Ws[e*33 + 2*f + 1] = u.y;
        }
        __syncthreads();

#pragma unroll 8
        for (int dp = 0; dp < 32; dp++) {
            ull w0 = Ws[(eg     )*33 + dp];
            ull w1 = Ws[(eg + 16)*33 + dp];
            ull w2 = Ws[(eg + 32)*33 + dp];
            ull w3 = Ws[(eg + 48)*33 + dp];
#pragma unroll
            for (int i = 0; i < 8; i++) {
                ull a = As[(rowg*8 + i)*34 + dp];
                fma2(acc[i][0], a, w0);
                fma2(acc[i][1], a, w1);
                fma2(acc[i][2], a, w2);
                fma2(acc[i][3], a, w3);
            }
        }
    }

#pragma unroll
    for (int i = 0; i < 8; i++) {
        int gr = row0 + rowg*8 + i;
        int bb = gr >> 11;
        int s  = gr & (SS-1);
        size_t base;
        if (p < 8) base = ((size_t)(bb*NH + h)*SS + s)*DKK;
        else       base = (size_t)gr*DKK;
#pragma unroll
        for (int j = 0; j < 4; j++) {
            int e = eg + 16*j;
            float2 xy = upk(acc[i][j]);
            dst[base + e] = (xy.x + xy.y + bias[e]) * scale;
        }
    }
}

// =====================================================================
// Kernel 1b: repack Q/K fp32 -> bf16x2 hi/lo planes. grid(8192,2), blk 256.
// =====================================================================
__global__ __launch_bounds__(256) void repack_qk_kernel()
{
    int t = blockIdx.x * 256 + threadIdx.x;          // pair index
    const float2* src = (const float2*)(blockIdx.y ? g_ks : g_qs);
    u32* dhi = blockIdx.y ? g_khi : g_qhi;
    u32* dlo = blockIdx.y ? g_klo : g_qlo;
    float2 p = src[t];
    u32 hi, lo; split2(p, hi, lo);
    dhi[t] = hi; dlo[t] = lo;
}

// =====================================================================
// Kernel 1c: V -> transposed bf16x2 hi/lo. grid(2048), blk 256.
//   out [b][e][sp] ; in g_vs[b*2048 + 2sp..][e]
// =====================================================================
__global__ __launch_bounds__(256) void repack_v_kernel()
{
    int t = blockIdx.x * 256 + threadIdx.x;          // 0..524287
    int b  = t >> 16;
    int r  = t & 65535;
    int e  = r >> 10;
    int sp = r & 1023;
    float v0 = g_vs[((size_t)b*SS + 2*sp    )*DKK + e];
    float v1 = g_vs[((size_t)b*SS + 2*sp + 1)*DKK + e];
    u32 hi, lo; split2(make_float2(v0, v1), hi, lo);
    g_vthi[t] = hi; g_vtlo[t] = lo;
}

// =====================================================================
// Kernel 2: fused attention, bf16 3-pass mma. grid(128,4,8), blk 256.
// =====================================================================
#define SPITCH 2052
#define KSP 36      // u32 pitch, K smem plane
#define VSP 68      // u32 pitch, Vt smem plane
#define SM2_U32 (16*SPITCH + 2*128*KSP + 16)   // 42,064 u32 = 168,256 B

__global__ __launch_bounds__(256) void attn_kernel(float* __restrict__ attn_out)
{
    extern __shared__ u32 smu[];
    float* S_   = (float*)smu;                // 16 x 2052 fp32
    u32* KH     = smu + 16*SPITCH;            // [128][36]
    u32* KL     = KH + 128*KSP;               // [128][36]
    u32* VH     = smu + 16*SPITCH;            // alias: [64][68]
    u32* VL     = VH + 64*VSP;                // [64][68]
    float* invrow = (float*)(smu + 16*SPITCH + 2*128*KSP);

    int b  = blockIdx.z;
    int h  = blockIdx.y;
    int q0 = blockIdx.x * 16;
    int tid  = threadIdx.x;
    int w    = tid >> 5;
    int lane = tid & 31;
    int gid  = lane >> 2;    // 0..7
    int tg   = lane & 3;     // 0..3

    size_t bh = (size_t)(b*NH + h)*SS;
    const u32* qhi = g_qhi + bh*32;
    const u32* qlo = g_qlo + bh*32;
    const u32* khi = g_khi + bh*32;
    const u32* klo = g_klo + bh*32;
    const u32* vthi = g_vthi + (size_t)b*DKK*1024;
    const u32* vtlo = g_vtlo + (size_t)b*DKK*1024;

    // ---- Q A-fragments from gmem: 4 k-steps x 4 regs, hi & lo ----
    u32 qh[4][4], ql[4][4];
#pragma unroll
    for (int ks = 0; ks < 4; ks++) {
        int o0 = (q0 + gid    )*32 + ks*8 + tg;
        int o1 = (q0 + gid + 8)*32 + ks*8 + tg;
        qh[ks][0] = qhi[o0];     qh[ks][1] = qhi[o1];
        qh[ks][2] = qhi[o0 + 4]; qh[ks][3] = qhi[o1 + 4];
        ql[ks][0] = qlo[o0];     ql[ks][1] = qlo[o1];
        ql[ks][2] = qlo[o0 + 4]; ql[ks][3] = qlo[o1 + 4];
    }

    // ---- Phase 1: scores. 16 tiles x 128 keys; warp owns 16 keys/tile ----
    int keyw = w * 16;
    for (int kt = 0; kt < 16; kt++) {
        int k0 = kt * 128;
        __syncthreads();
        // stage K hi/lo planes: 128 keys x 32 u32 each
#pragma unroll
        for (int i = 0; i < 4; i++) {
            int f4 = tid + i*256;
            int key = f4 >> 3, fo = (f4 & 7) * 4;
            *(uint4*)&KH[key*KSP + fo] = *(const uint4*)&khi[(size_t)(k0 + key)*32 + fo];
            *(uint4*)&KL[key*KSP + fo] = *(const uint4*)&klo[(size_t)(k0 + key)*32 + fo];
        }
        __syncthreads();

        float chh0[4] = {0,0,0,0}, chl0[4] = {0,0,0,0}, clh0[4] = {0,0,0,0};
        float chh1[4] = {0,0,0,0}, chl1[4] = {0,0,0,0}, clh1[4] = {0,0,0,0};
#pragma unroll
        for (int ks = 0; ks < 4; ks++) {
            int ko0 = (keyw + gid    )*KSP + ks*8 + tg;
            int ko1 = (keyw + gid + 8)*KSP + ks*8 + tg;
            u32 bh0 = KH[ko0], bh1 = KH[ko0 + 4];
            u32 bl0 = KL[ko0], bl1 = KL[ko0 + 4];
            u32 ch0 = KH[ko1], ch1 = KH[ko1 + 4];
            u32 cl0 = KL[ko1], cl1 = KL[ko1 + 4];
            mma_bf(chh0, qh[ks], bh0, bh1);
            mma_bf(chh1, qh[ks], ch0, ch1);
            mma_bf(chl0, qh[ks], bl0, bl1);
            mma_bf(chl1, qh[ks], cl0, cl1);
            mma_bf(clh0, ql[ks], bh0, bh1);
            mma_bf(clh1, ql[ks], ch0, ch1);
        }
        float s00 = chh0[0]+chl0[0]+clh0[0], s01 = chh0[1]+chl0[1]+clh0[1];
        float s02 = chh0[2]+chl0[2]+clh0[2], s03 = chh0[3]+chl0[3]+clh0[3];
        float s10 = chh1[0]+chl1[0]+clh1[0], s11 = chh1[1]+chl1[1]+clh1[1];
        float s12 = chh1[2]+chl1[2]+clh1[2], s13 = chh1[3]+chl1[3]+clh1[3];
        *(float2*)&S_[gid*SPITCH     + k0 + keyw     + tg*2] = make_float2(s00, s01);
        *(float2*)&S_[(gid+8)*SPITCH + k0 + keyw     + tg*2] = make_float2(s02, s03);
        *(float2*)&S_[gid*SPITCH     + k0 + keyw + 8 + tg*2] = make_float2(s10, s11);
        *(float2*)&S_[(gid+8)*SPITCH + k0 + keyw + 8 + tg*2] = make_float2(s12, s13);
    }
    __syncthreads();

    // ---- Phase 2: softmax (unnormalized exp kept in S_) ----
    {
        int row = tid >> 4;
        int l16 = tid & 15;
        float4* S4 = (float4*)(S_ + row*SPITCH);
        float m = -1e30f;
#pragma unroll 8
        for (int i = 0; i < 32; i++) {
            float4 x = S4[i*16 + l16];
            m = fmaxf(m, fmaxf(fmaxf(x.x, x.y), fmaxf(x.z, x.w)));
        }
#pragma unroll
        for (int off = 8; off >= 1; off >>= 1)
            m = fmaxf(m, __shfl_xor_sync(0xffffffffu, m, off));
        float ssum = 0.0f;
#pragma unroll 4
        for (int i = 0; i < 32; i++) {
            int idx = i*16 + l16;
            float4 x = S4[idx];
            x.x = __expf(x.x - m); x.y = __expf(x.y - m);
            x.z = __expf(x.z - m); x.w = __expf(x.w - m);
            S4[idx] = x;
            ssum += (x.x + x.y) + (x.z + x.w);
        }
#pragma unroll
        for (int off = 8; off >= 1; off >>= 1)
            ssum += __shfl_xor_sync(0xffffffffu, ssum, off);
        if (l16 == 0) invrow[row] = 1.0f / ssum;
    }
    __syncthreads();

    // ---- Phase 2b: normalized attn -> gmem ----
    {
        float* ab = attn_out + (((size_t)b*SS + q0)*NH + h)*SS;
#pragma unroll 4
        for (int it = 0; it < 32; it++) {
            int slot = tid + it*256;
            int r  = slot >> 9;
            int c4 = slot & 511;
            float4 x = ((float4*)(S_ + r*SPITCH))[c4];
            float inv = invrow[r];
            x.x *= inv; x.y *= inv; x.z *= inv; x.w *= inv;
            ((float4*)(ab + (size_t)r*NH*SS))[c4] = x;
        }
    }

    // ---- Phase 3: PV via bf16 3-pass mma. Warp owns e0 = w*8 ----
    int e0 = w * 8;
    float phh[2][4], phl[2][4], plh[2][4];
#pragma unroll
    for (int p2 = 0; p2 < 2; p2++)
#pragma unroll
        for (int j = 0; j < 4; j++) { phh[p2][j] = 0.f; phl[p2][j] = 0.f; plh[p2][j] = 0.f; }

    for (int kt = 0; kt < 16; kt++) {
        int k0 = kt * 128;
        __syncthreads();
        // stage Vt hi/lo planes: 64 e x 64 u32 each
#pragma unroll
        for (int i = 0; i < 4; i++) {
            int f4 = tid + i*256;
            int e = f4 >> 4, fo = (f4 & 15) * 4;
            *(uint4*)&VH[e*VSP + fo] = *(const uint4*)&vthi[(size_t)e*1024 + k0/2 + fo];
            *(uint4*)&VL[e*VSP + fo] = *(const uint4*)&vtlo[(size_t)e*1024 + k0/2 + fo];
        }
        __syncthreads();
#pragma unroll
        for (int ks = 0; ks < 8; ks++) {
            int kb = k0 + ks*16;
            int p2 = ks & 1;
            // A fragments from fp32 P, split to hi/lo
            float2 p00 = *(float2*)&S_[gid*SPITCH     + kb + 2*tg];
            float2 p10 = *(float2*)&S_[(gid+8)*SPITCH + kb + 2*tg];
            float2 p01 = *(float2*)&S_[gid*SPITCH     + kb + 2*tg + 8];
            float2 p11 = *(float2*)&S_[(gid+8)*SPITCH + kb + 2*tg + 8];
            u32 ah[4], al[4];
            split2(p00, ah[0], al[0]);
            split2(p10, ah[1], al[1]);
            split2(p01, ah[2], al[2]);
            split2(p11, ah[3], al[3]);
            int vo = (e0 + gid)*VSP + ks*8 + tg;
            u32 b0h = VH[vo], b1h = VH[vo + 4];
            u32 b0l = VL[vo], b1l = VL[vo + 4];
            mma_bf(phh[p2], ah, b0h, b1h);
            mma_bf(phl[p2], ah, b0l, b1l);
            mma_bf(plh[p2], al, b0h, b1h);
        }
    }
    // ---- PV epilogue: combine, normalize, store heads ----
    {
        float inv_lo = invrow[gid];
        float inv_hi = invrow[gid + 8];
        float o0 = (phh[0][0]+phh[1][0]+phl[0][0]+phl[1][0]+plh[0][0]+plh[1][0]) * inv_lo;
        float o1 = (phh[0][1]+phh[1][1]+phl[0][1]+phl[1][1]+plh[0][1]+plh[1][1]) * inv_lo;
        float o2 = (phh[0][2]+phh[1][2]+phl[0][2]+phl[1][2]+plh[0][2]+plh[1][2]) * inv_hi;
        float o3 = (phh[0][3]+phh[1][3]+phl[0][3]+phl[1][3]+plh[0][3]+plh[1][3]) * inv_hi;
        size_t hb = bh + q0;
        *(float2*)&g_heads[(hb + gid    )*DKK + e0 + tg*2] = make_float2(o0, o1);
        *(float2*)&g_heads[(hb + gid + 8)*DKK + e0 + tg*2] = make_float2(o2, o3);
    }
}

// =====================================================================
// Kernel 3: head-average + output projection.
// =====================================================================
#define SMEM3_FLOATS (64*68 + 64*260)

__global__ __launch_bounds__(256) void outproj_kernel(
    const float* __restrict__ Wh, float* __restrict__ out)
{
    extern __shared__ float sm[];
    float* AvT = sm;             // [e][s] 64x68
    float* WhT = sm + 64*68;     // [e][dm] 64x260

    int s0 = blockIdx.x * 64;
    int tid = threadIdx.x;

#pragma unroll
    for (int i = 0; i < 16; i++) {
        int idx = tid + i*256;
        int sl = idx >> 6, e = idx & 63;
        int gr = s0 + sl;
        int bb = gr >> 11, s = gr & (SS-1);
        size_t base = ((size_t)bb*NH*SS + s)*DKK + e;
        float sum = g_heads[base]
                  + g_heads[base + (size_t)SS*DKK]
                  + g_heads[base + (size_t)2*SS*DKK]
                  + g_heads[base + (size_t)3*SS*DKK];
        AvT[e*68 + sl] = 0.25f * sum;
    }
#pragma unroll
    for (int i = 0; i < 64; i++) {
        int idx = tid + i*256;
        int dm = idx >> 6, e = idx & 63;
        WhT[e*260 + dm] = Wh[dm*DKK + e];
    }
    __syncthreads();

    int ts = tid >> 5;
    int tc = tid & 31;
    float acc[8][8];
#pragma unroll
    for (int i = 0; i < 8; i++)
#pragma unroll
        for (int j = 0; j < 8; j++) acc[i][j] = 0.0f;

#pragma unroll 8
    for (int e = 0; e < 64; e++) {
        float4 a0 = *(float4*)(AvT + e*68 + ts*8);
        float4 a1 = *(float4*)(AvT + e*68 + ts*8 + 4);
        float4 w0 = *(float4*)(WhT + e*260 + tc*8);
        float4 w1 = *(float4*)(WhT + e*260 + tc*8 + 4);
        float a[8] = {a0.x,a0.y,a0.z,a0.w,a1.x,a1.y,a1.z,a1.w};
        float wv[8] = {w0.x,w0.y,w0.z,w0.w,w1.x,w1.y,w1.z,w1.w};
#pragma unroll
        for (int i = 0; i < 8; i++)
#pragma unroll
            for (int j = 0; j < 8; j++) acc[i][j] = fmaf(a[i], wv[j], acc[i][j]);
    }
#pragma unroll
    for (int i = 0; i < 8; i++) {
        int gr = s0 + ts*8 + i;
        float4 o0 = make_float4(acc[i][0], acc[i][1], acc[i][2], acc[i][3]);
        float4 o1 = make_float4(acc[i][4], acc[i][5], acc[i][6], acc[i][7]);
        *(float4*)(out + (size_t)gr*DM + tc*8)     = o0;
        *(float4*)(out + (size_t)gr*DM + tc*8 + 4) = o1;
    }
}

// =====================================================================
extern "C" void kernel_launch(void* const* d_in, const int* in_sizes, int n_in,
                              void* d_out, int out_size)
{
    const float* q  = (const float*)d_in[0];
    const float* k  = (const float*)d_in[1];
    const float* v  = (const float*)d_in[2];
    const float* Wq = (const float*)d_in[3];
    const float* bq = (const float*)d_in[4];
    const float* Wk = (const float*)d_in[5];
    const float* bk = (const float*)d_in[6];
    const float* Wv = (const float*)d_in[7];
    const float* bv = (const float*)d_in[8];
    const float* Wh = (const float*)d_in[9];

    float* out  = (float*)d_out;                       // [B,S,DM]
    float* attn = out + (size_t)BB*SS*DM;              // [B,S,H,S]

    cudaFuncSetAttribute(proj_kernel, cudaFuncAttributeMaxDynamicSharedMemorySize,
                         PROJ_SMEM_BYTES);
    cudaFuncSetAttribute(attn_kernel, cudaFuncAttributeMaxDynamicSharedMemorySize,
                         SM2_U32 * 4);
    cudaFuncSetAttribute(outproj_kernel, cudaFuncAttributeMaxDynamicSharedMemorySize,
                         SMEM3_FLOATS * sizeof(float));

    proj_kernel<<<dim3(NROWS/128, 9), 256, PROJ_SMEM_BYTES>>>(q, k, v, Wq, bq, Wk, bk, Wv, bv);
    repack_qk_kernel<<<dim3(QKPAIRS/256, 2), 256>>>();
    repack_v_kernel<<<VTP/256, 256>>>();
    attn_kernel<<<dim3(SS/16, NH, BB), 256, SM2_U32 * 4>>>(attn);
    outproj_kernel<<<NROWS/64, 256, SMEM3_FLOATS * sizeof(float)>>>(Wh, out);
}

// round 5
// speedup vs baseline: 2.7329x; 1.9140x over previous
#include <cuda_runtime.h>
#include <cuda_bf16.h>
#include <math.h>

typedef unsigned long long ull;
typedef unsigned int u32;

#define BB 8
#define SS 2048
#define DM 256
#define NH 4
#define DKK 64
#define NROWS (BB*SS)   // 16384

// ---- scratch (static device, no allocations) ----
__device__ float g_qs[BB*NH*SS*DKK];     // pre-scaled by 1/8
__device__ float g_ks[BB*NH*SS*DKK];
__device__ float g_vs[BB*SS*DKK];
__device__ float g_heads[BB*NH*SS*DKK];
#define QKPAIRS (BB*NH*SS*32)            // 2,097,152
__device__ u32 g_qhi[QKPAIRS];
__device__ u32 g_qlo[QKPAIRS];
__device__ u32 g_khi[QKPAIRS];
__device__ u32 g_klo[QKPAIRS];
#define VTP (BB*DKK*(SS/2))              // 524,288
__device__ u32 g_vthi[VTP];
__device__ u32 g_vtlo[VTP];
__device__ float2 g_stats[NROWS*NH];     // (rowmax, 1/sum) per attn row

// ---- packed fp32x2 helpers (proj kernel) ----
__device__ __forceinline__ void fma2(ull& d, ull a, ull b) {
    asm("fma.rn.f32x2 %0, %1, %2, %0;" : "+l"(d) : "l"(a), "l"(b));
}
__device__ __forceinline__ float2 upk(ull v) {
    float2 r; asm("mov.b64 {%0, %1}, %2;" : "=f"(r.x), "=f"(r.y) : "l"(v)); return r;
}

// ---- bf16 helpers ----
__device__ __forceinline__ u32 bf2(float lo, float hi) {
    u32 r; asm("cvt.rn.bf16x2.f32 %0, %1, %2;" : "=r"(r) : "f"(hi), "f"(lo)); return r;
}
__device__ __forceinline__ float bflo(u32 p) { return __uint_as_float(p << 16); }
__device__ __forceinline__ float bfhi(u32 p) { return __uint_as_float(p & 0xffff0000u); }
__device__ __forceinline__ void split2(float2 p, u32& hi, u32& lo) {
    hi = bf2(p.x, p.y);
    lo = bf2(p.x - bflo(hi), p.y - bfhi(hi));
}

// ---- bf16 mma m16n8k16, fp32 accumulate ----
__device__ __forceinline__ void mma_bf(float* c, const u32* a, u32 b0, u32 b1) {
    asm volatile("mma.sync.aligned.m16n8k16.row.col.f32.bf16.bf16.f32 "
        "{%0,%1,%2,%3}, {%4,%5,%6,%7}, {%8,%9}, {%0,%1,%2,%3};"
        : "+f"(c[0]), "+f"(c[1]), "+f"(c[2]), "+f"(c[3])
        : "r"(a[0]), "r"(a[1]), "r"(a[2]), "r"(a[3]), "r"(b0), "r"(b1));
}

// =====================================================================
// Kernel 1: projections (FFMA2). grid(128,9), blk 256.
// =====================================================================
#define PROJ_SMEM_BYTES ((128*34 + 64*33) * 8)

__global__ __launch_bounds__(256) void proj_kernel(
    const float* __restrict__ qin, const float* __restrict__ kin,
    const float* __restrict__ vin,
    const float* __restrict__ Wq, const float* __restrict__ bq,
    const float* __restrict__ Wk, const float* __restrict__ bk,
    const float* __restrict__ Wv, const float* __restrict__ bv)
{
    extern __shared__ ull smp[];
    ull* As = smp;            // [128][34]
    ull* Ws = smp + 128*34;   // [64][33]

    int p = blockIdx.y;
    const float *A, *W, *bias;
    float scale; float* dst; int h = 0;
    if (p < 4)      { h = p;   A = qin; W = Wq + h*DKK*DM; bias = bq + h*DKK; scale = 0.125f; dst = g_qs; }
    else if (p < 8) { h = p-4; A = kin; W = Wk + h*DKK*DM; bias = bk + h*DKK; scale = 1.0f;   dst = g_ks; }
    else            {          A = vin; W = Wv;            bias = bv;         scale = 1.0f;   dst = g_vs; }

    int row0 = blockIdx.x * 128;
    int tid  = threadIdx.x;
    int rowg = tid >> 4;
    int eg   = tid & 15;

    ull acc[8][4];
#pragma unroll
    for (int i = 0; i < 8; i++)
#pragma unroll
        for (int j = 0; j < 4; j++) acc[i][j] = 0ull;

    for (int d0 = 0; d0 < DM; d0 += 64) {
        __syncthreads();
#pragma unroll
        for (int i = 0; i < 8; i++) {
            int f4 = tid + i*256;
            int r = f4 >> 4, f = f4 & 15;
            float4 v = *(const float4*)(A + (size_t)(row0 + r)*DM + d0 + f*4);
            *(float4*)&As[r*34 + 2*f] = v;
        }
#pragma unroll
        for (int i = 0; i < 4; i++) {
            int f4 = tid + i*256;
            int e = f4 >> 4, f = f4 & 15;
            float4 v = *(const float4*)(W + (size_t)e*DM + d0 + f*4);
            ulonglong2 u = *(ulonglong2*)&v;
            Ws[e*33 + 2*f]     = u.x;
            Ws[e*33 + 2*f + 1] = u.y;
        }
        __syncthreads();

#pragma unroll 8
        for (int dp = 0; dp < 32; dp++) {
            ull w0 = Ws[(eg     )*33 + dp];
            ull w1 = Ws[(eg + 16)*33 + dp];
            ull w2 = Ws[(eg + 32)*33 + dp];
            ull w3 = Ws[(eg + 48)*33 + dp];
#pragma unroll
            for (int i = 0; i < 8; i++) {
                ull a = As[(rowg*8 + i)*34 + dp];
                fma2(acc[i][0], a, w0);
                fma2(acc[i][1], a, w1);
                fma2(acc[i][2], a, w2);
                fma2(acc[i][3], a, w3);
            }
        }
    }

#pragma unroll
    for (int i = 0; i < 8; i++) {
        int gr = row0 + rowg*8 + i;
        int bb = gr >> 11;
        int s  = gr & (SS-1);
        size_t base;
        if (p < 8) base = ((size_t)(bb*NH + h)*SS + s)*DKK;
        else       base = (size_t)gr*DKK;
#pragma unroll
        for (int j = 0; j < 4; j++) {
            int e = eg + 16*j;
            float2 xy = upk(acc[i][j]);
            dst[base + e] = (xy.x + xy.y + bias[e]) * scale;
        }
    }
}

// =====================================================================
// Kernel 1b/1c: repack to bf16 hi/lo planes.
// =====================================================================
__global__ __launch_bounds__(256) void repack_qk_kernel()
{
    int t = blockIdx.x * 256 + threadIdx.x;
    const float2* src = (const float2*)(blockIdx.y ? g_ks : g_qs);
    u32* dhi = blockIdx.y ? g_khi : g_qhi;
    u32* dlo = blockIdx.y ? g_klo : g_qlo;
    float2 p = src[t];
    u32 hi, lo; split2(p, hi, lo);
    dhi[t] = hi; dlo[t] = lo;
}

__global__ __launch_bounds__(256) void repack_v_kernel()
{
    int t = blockIdx.x * 256 + threadIdx.x;
    int b  = t >> 16;
    int r  = t & 65535;
    int e  = r >> 10;
    int sp = r & 1023;
    float v0 = g_vs[((size_t)b*SS + 2*sp    )*DKK + e];
    float v1 = g_vs[((size_t)b*SS + 2*sp + 1)*DKK + e];
    u32 hi, lo; split2(make_float2(v0, v1), hi, lo);
    g_vthi[t] = hi; g_vtlo[t] = lo;
}

// =====================================================================
// Kernel 2: scores GEMM. grid(16 ktile, 16 qtile, 32 bh), blk 256.
//   Writes RAW scores into attn_out. smem 73,728 B; 2 CTAs/SM.
// =====================================================================
#define SCP 36
#define SCORES_SMEM (4*128*SCP*4)

__global__ __launch_bounds__(256, 2) void scores_kernel(float* __restrict__ attn)
{
    extern __shared__ u32 smu[];
    u32* QH = smu;
    u32* QL = QH + 128*SCP;
    u32* KH = QL + 128*SCP;
    u32* KL = KH + 128*SCP;

    int bh = blockIdx.z;
    int b = bh >> 2, h = bh & 3;
    int q0 = blockIdx.y * 128;
    int k0 = blockIdx.x * 128;
    int tid  = threadIdx.x;
    int w    = tid >> 5;
    int lane = tid & 31;
    int gid  = lane >> 2;
    int tg   = lane & 3;

    const u32* qhi = g_qhi + (size_t)bh*SS*32;
    const u32* qlo = g_qlo + (size_t)bh*SS*32;
    const u32* khi = g_khi + (size_t)bh*SS*32;
    const u32* klo = g_klo + (size_t)bh*SS*32;

    // stage Q & K tiles (hi/lo planes): 128 rows x 32 u32 each
#pragma unroll
    for (int i = 0; i < 4; i++) {
        int f4 = tid + i*256;
        int r = f4 >> 3, fo = (f4 & 7) * 4;
        *(uint4*)&QH[r*SCP + fo] = *(const uint4*)&qhi[(size_t)(q0 + r)*32 + fo];
        *(uint4*)&QL[r*SCP + fo] = *(const uint4*)&qlo[(size_t)(q0 + r)*32 + fo];
        *(uint4*)&KH[r*SCP + fo] = *(const uint4*)&khi[(size_t)(k0 + r)*32 + fo];
        *(uint4*)&KL[r*SCP + fo] = *(const uint4*)&klo[(size_t)(k0 + r)*32 + fo];
    }
    __syncthreads();

    int wq = w >> 2;   // 0..1 : 64 q rows
    int wk = w & 3;    // 0..3 : 32 k cols

    float acc[4][4][4];
#pragma unroll
    for (int mt = 0; mt < 4; mt++)
#pragma unroll
        for (int nt = 0; nt < 4; nt++)
#pragma unroll
            for (int j = 0; j < 4; j++) acc[mt][nt][j] = 0.0f;

#pragma unroll
    for (int ks = 0; ks < 4; ks++) {
        u32 bh_[4][2], bl_[4][2];
#pragma unroll
        for (int nt = 0; nt < 4; nt++) {
            int n = wk*32 + nt*8 + gid;
            bh_[nt][0] = KH[n*SCP + ks*8 + tg];
            bh_[nt][1] = KH[n*SCP + ks*8 + tg + 4];
            bl_[nt][0] = KL[n*SCP + ks*8 + tg];
            bl_[nt][1] = KL[n*SCP + ks*8 + tg + 4];
        }
#pragma unroll
        for (int mt = 0; mt < 4; mt++) {
            int r = wq*64 + mt*16;
            u32 ah[4], al[4];
            ah[0] = QH[(r + gid    )*SCP + ks*8 + tg];
            ah[1] = QH[(r + gid + 8)*SCP + ks*8 + tg];
            ah[2] = QH[(r + gid    )*SCP + ks*8 + tg + 4];
            ah[3] = QH[(r + gid + 8)*SCP + ks*8 + tg + 4];
            al[0] = QL[(r + gid    )*SCP + ks*8 + tg];
            al[1] = QL[(r + gid + 8)*SCP + ks*8 + tg];
            al[2] = QL[(r + gid    )*SCP + ks*8 + tg + 4];
            al[3] = QL[(r + gid + 8)*SCP + ks*8 + tg + 4];
#pragma unroll
            for (int nt = 0; nt < 4; nt++) {
                mma_bf(acc[mt][nt], ah, bh_[nt][0], bh_[nt][1]);
                mma_bf(acc[mt][nt], ah, bl_[nt][0], bl_[nt][1]);
                mma_bf(acc[mt][nt], al, bh_[nt][0], bh_[nt][1]);
            }
        }
    }

    // epilogue: raw scores -> attn[b][q][h][k0..]
    float* ab = attn + (((size_t)b*SS + q0)*NH + h)*SS + k0;
#pragma unroll
    for (int mt = 0; mt < 4; mt++) {
        int r = wq*64 + mt*16 + gid;
#pragma unroll
        for (int nt = 0; nt < 4; nt++) {
            int c = wk*32 + nt*8 + 2*tg;
            *(float2*)&ab[(size_t)r*NH*SS + c]       = make_float2(acc[mt][nt][0], acc[mt][nt][1]);
            *(float2*)&ab[(size_t)(r + 8)*NH*SS + c] = make_float2(acc[mt][nt][2], acc[mt][nt][3]);
        }
    }
}

// =====================================================================
// Kernel 3: row stats (max, 1/sum). grid(8192), blk 256: 1 warp/row.
// =====================================================================
__global__ __launch_bounds__(256) void stats_kernel(const float* __restrict__ attn)
{
    int r = blockIdx.x * 8 + (threadIdx.x >> 5);
    int lane = threadIdx.x & 31;
    const float4* row = (const float4*)(attn + (size_t)r*SS);
    float m = -1e30f;
#pragma unroll
    for (int i = 0; i < 16; i++) {
        float4 x = row[lane + i*32];
        m = fmaxf(m, fmaxf(fmaxf(x.x, x.y), fmaxf(x.z, x.w)));
    }
#pragma unroll
    for (int off = 16; off >= 1; off >>= 1)
        m = fmaxf(m, __shfl_xor_sync(0xffffffffu, m, off));
    float s = 0.0f;
#pragma unroll
    for (int i = 0; i < 16; i++) {
        float4 x = row[lane + i*32];
        s += __expf(x.x - m) + __expf(x.y - m) + __expf(x.z - m) + __expf(x.w - m);
    }
#pragma unroll
    for (int off = 16; off >= 1; off >>= 1)
        s += __shfl_xor_sync(0xffffffffu, s, off);
    if (lane == 0) g_stats[r] = make_float2(m, 1.0f / s);
}

// =====================================================================
// Kernel 4: PV + in-place normalize. grid(16 qtile, 32 bh), blk 256.
//   Reads raw S from attn, writes normalized attn back, accumulates PV.
// =====================================================================
#define VDP 68
#define PV_SMEM (2*64*VDP*4)

__global__ __launch_bounds__(256, 2) void pv_kernel(float* __restrict__ attn)
{
    extern __shared__ u32 smu[];
    u32* VH = smu;
    u32* VL = VH + 64*VDP;

    int bh = blockIdx.y;
    int b = bh >> 2, h = bh & 3;
    int q0 = blockIdx.x * 128;
    int tid  = threadIdx.x;
    int w    = tid >> 5;
    int lane = tid & 31;
    int gid  = lane >> 2;
    int tg   = lane & 3;

    const u32* vh = g_vthi + (size_t)b*DKK*1024;
    const u32* vl = g_vtlo + (size_t)b*DKK*1024;

    // per-row stats for this warp's 16 rows
    int qa = q0 + w*16 + gid;
    float2 st0 = g_stats[(size_t)(b*SS + qa    )*NH + h];
    float2 st1 = g_stats[(size_t)(b*SS + qa + 8)*NH + h];
    float m0 = st0.x, i0 = st0.y;
    float m1 = st1.x, i1 = st1.y;

    float* rlo = attn + (((size_t)b*SS + qa    )*NH + h)*SS;
    float* rhi = attn + (((size_t)b*SS + qa + 8)*NH + h)*SS;

    float acc[8][4];
#pragma unroll
    for (int nt = 0; nt < 8; nt++)
#pragma unroll
        for (int j = 0; j < 4; j++) acc[nt][j] = 0.0f;

    for (int kt = 0; kt < 16; kt++) {
        int k0 = kt * 128;
        __syncthreads();
        // stage V tile hi/lo: 64 e x 64 u32 (128 keys)
#pragma unroll
        for (int i = 0; i < 4; i++) {
            int f4 = tid + i*256;
            int e = f4 >> 4, fo = (f4 & 15) * 4;
            *(uint4*)&VH[e*VDP + fo] = *(const uint4*)&vh[(size_t)e*1024 + k0/2 + fo];
            *(uint4*)&VL[e*VDP + fo] = *(const uint4*)&vl[(size_t)e*1024 + k0/2 + fo];
        }
        __syncthreads();

#pragma unroll
        for (int ks = 0; ks < 8; ks++) {
            int c = k0 + ks*16 + 2*tg;
            float2 p00 = *(float2*)&rlo[c];
            float2 p10 = *(float2*)&rhi[c];
            float2 p01 = *(float2*)&rlo[c + 8];
            float2 p11 = *(float2*)&rhi[c + 8];
            p00.x = __expf(p00.x - m0) * i0;  p00.y = __expf(p00.y - m0) * i0;
            p10.x = __expf(p10.x - m1) * i1;  p10.y = __expf(p10.y - m1) * i1;
            p01.x = __expf(p01.x - m0) * i0;  p01.y = __expf(p01.y - m0) * i0;
            p11.x = __expf(p11.x - m1) * i1;  p11.y = __expf(p11.y - m1) * i1;
            *(float2*)&rlo[c]     = p00;
            *(float2*)&rhi[c]     = p10;
            *(float2*)&rlo[c + 8] = p01;
            *(float2*)&rhi[c + 8] = p11;
            u32 ah[4], al[4];
            split2(p00, ah[0], al[0]);
            split2(p10, ah[1], al[1]);
            split2(p01, ah[2], al[2]);
            split2(p11, ah[3], al[3]);
#pragma unroll
            for (int nt = 0; nt < 8; nt++) {
                int vo = (nt*8 + gid)*VDP + ks*8 + tg;
                u32 b0 = VH[vo], b1 = VH[vo + 4];
                u32 c0 = VL[vo], c1 = VL[vo + 4];
                mma_bf(acc[nt], ah, b0, b1);
                mma_bf(acc[nt], ah, c0, c1);
                mma_bf(acc[nt], al, b0, b1);
            }
        }
    }

    // epilogue: heads
    size_t hb = (size_t)bh*SS + q0 + w*16;
#pragma unroll
    for (int nt = 0; nt < 8; nt++) {
        int e = nt*8 + 2*tg;
        *(float2*)&g_heads[(hb + gid    )*DKK + e] = make_float2(acc[nt][0], acc[nt][1]);
        *(float2*)&g_heads[(hb + gid + 8)*DKK + e] = make_float2(acc[nt][2], acc[nt][3]);
    }
}

// =====================================================================
// Kernel 5: head-average + output projection.
// =====================================================================
#define SMEM3_FLOATS (64*68 + 64*260)

__global__ __launch_bounds__(256) void outproj_kernel(
    const float* __restrict__ Wh, float* __restrict__ out)
{
    extern __shared__ float sm[];
    float* AvT = sm;             // [e][s] 64x68
    float* WhT = sm + 64*68;     // [e][dm] 64x260

    int s0 = blockIdx.x * 64;
    int tid = threadIdx.x;

#pragma unroll
    for (int i = 0; i < 16; i++) {
        int idx = tid + i*256;
        int sl = idx >> 6, e = idx & 63;
        int gr = s0 + sl;
        int bb = gr >> 11, s = gr & (SS-1);
        size_t base = ((size_t)bb*NH*SS + s)*DKK + e;
        float sum = g_heads[base]
                  + g_heads[base + (size_t)SS*DKK]
                  + g_heads[base + (size_t)2*SS*DKK]
                  + g_heads[base + (size_t)3*SS*DKK];
        AvT[e*68 + sl] = 0.25f * sum;
    }
#pragma unroll
    for (int i = 0; i < 64; i++) {
        int idx = tid + i*256;
        int dm = idx >> 6, e = idx & 63;
        WhT[e*260 + dm] = Wh[dm*DKK + e];
    }
    __syncthreads();

    int ts = tid >> 5;
    int tc = tid & 31;
    float acc[8][8];
#pragma unroll
    for (int i = 0; i < 8; i++)
#pragma unroll
        for (int j = 0; j < 8; j++) acc[i][j] = 0.0f;

#pragma unroll 8
    for (int e = 0; e < 64; e++) {
        float4 a0 = *(float4*)(AvT + e*68 + ts*8);
        float4 a1 = *(float4*)(AvT + e*68 + ts*8 + 4);
        float4 w0 = *(float4*)(WhT + e*260 + tc*8);
        float4 w1 = *(float4*)(WhT + e*260 + tc*8 + 4);
        float a[8] = {a0.x,a0.y,a0.z,a0.w,a1.x,a1.y,a1.z,a1.w};
        float wv[8] = {w0.x,w0.y,w0.z,w0.w,w1.x,w1.y,w1.z,w1.w};
#pragma unroll
        for (int i = 0; i < 8; i++)
#pragma unroll
            for (int j = 0; j < 8; j++) acc[i][j] = fmaf(a[i], wv[j], acc[i][j]);
    }
#pragma unroll
    for (int i = 0; i < 8; i++) {
        int gr = s0 + ts*8 + i;
        float4 o0 = make_float4(acc[i][0], acc[i][1], acc[i][2], acc[i][3]);
        float4 o1 = make_float4(acc[i][4], acc[i][5], acc[i][6], acc[i][7]);
        *(float4*)(out + (size_t)gr*DM + tc*8)     = o0;
        *(float4*)(out + (size_t)gr*DM + tc*8 + 4) = o1;
    }
}

// =====================================================================
extern "C" void kernel_launch(void* const* d_in, const int* in_sizes, int n_in,
                              void* d_out, int out_size)
{
    const float* q  = (const float*)d_in[0];
    const float* k  = (const float*)d_in[1];
    const float* v  = (const float*)d_in[2];
    const float* Wq = (const float*)d_in[3];
    const float* bq = (const float*)d_in[4];
    const float* Wk = (const float*)d_in[5];
    const float* bk = (const float*)d_in[6];
    const float* Wv = (const float*)d_in[7];
    const float* bv = (const float*)d_in[8];
    const float* Wh = (const float*)d_in[9];

    float* out  = (float*)d_out;                       // [B,S,DM]
    float* attn = out + (size_t)BB*SS*DM;              // [B,S,H,S]

    cudaFuncSetAttribute(proj_kernel, cudaFuncAttributeMaxDynamicSharedMemorySize,
                         PROJ_SMEM_BYTES);
    cudaFuncSetAttribute(scores_kernel, cudaFuncAttributeMaxDynamicSharedMemorySize,
                         SCORES_SMEM);
    cudaFuncSetAttribute(pv_kernel, cudaFuncAttributeMaxDynamicSharedMemorySize,
                         PV_SMEM);
    cudaFuncSetAttribute(outproj_kernel, cudaFuncAttributeMaxDynamicSharedMemorySize,
                         SMEM3_FLOATS * sizeof(float));

    proj_kernel<<<dim3(NROWS/128, 9), 256, PROJ_SMEM_BYTES>>>(q, k, v, Wq, bq, Wk, bk, Wv, bv);
    repack_qk_kernel<<<dim3(QKPAIRS/256, 2), 256>>>();
    repack_v_kernel<<<VTP/256, 256>>>();
    scores_kernel<<<dim3(16, 16, 32), 256, SCORES_SMEM>>>(attn);
    stats_kernel<<<NROWS*NH/8, 256>>>(attn);
    pv_kernel<<<dim3(16, 32), 256, PV_SMEM>>>(attn);
    outproj_kernel<<<NROWS/64, 256, SMEM3_FLOATS * sizeof(float)>>>(Wh, out);
}